// round 8
// baseline (speedup 1.0000x reference)
#include <cuda_runtime.h>

// Problem shapes (fixed)
#define BB 16
#define TT 256
#define NPTS 2048
#define NF (NPTS * 3)            // 6144 floats per frame-row
#define NC4 (NF / 4)             // 1536 float4-chunks per frame-row
#define TC 8                     // chunks over T
#define FR (TT / TC)             // 32 frames per thread
#define NSLOTS (BB * TC)         // 128
#define SLOTS_PER_BLK 8          // one slot per warp
#define C4_PER_BLK 32            // one warp-width of chunks
#define BLK 256
#define NSGRP (NSLOTS / SLOTS_PER_BLK)   // 16
#define NCGRP (NC4 / C4_PER_BLK)         // 48
#define NBLK (NSGRP * NCGRP)             // 768
#define NSTAT 5                  // cnt, sum_p, sumsq_p, sum_g, sumsq_g (per channel)

typedef unsigned long long ull;

// Device globals (no runtime allocation). g_red is atomically accumulated by
// k_main and RE-ZEROED by k_final each invocation (zero-init at module load).
__device__ float g_red[NSTAT * NF];      // 123 KB per-channel stats
__device__ float g_bsum[NBLK * 3];       // per-block recon/temporal/nvel

// ---- packed f32x2 helpers (sm_103a) --------------------------------------
__device__ __forceinline__ ull f2_mul(ull a, ull b) {
    ull d; asm("mul.rn.f32x2 %0,%1,%2;" : "=l"(d) : "l"(a), "l"(b)); return d;
}
__device__ __forceinline__ ull f2_add(ull a, ull b) {
    ull d; asm("add.rn.f32x2 %0,%1,%2;" : "=l"(d) : "l"(a), "l"(b)); return d;
}
__device__ __forceinline__ ull f2_fma(ull a, ull b, ull c) {
    ull d; asm("fma.rn.f32x2 %0,%1,%2,%3;" : "=l"(d) : "l"(a), "l"(b), "l"(c)); return d;
}
__device__ __forceinline__ ull f2_pack(float a, float b) {
    ull r; asm("mov.b64 %0,{%1,%2};" : "=l"(r) : "f"(a), "f"(b)); return r;
}
__device__ __forceinline__ void f2_unpack(ull v, float& x, float& y) {
    asm("mov.b64 {%0,%1},%2;" : "=f"(x), "=f"(y) : "l"(v));
}
__device__ __forceinline__ float f2_sum(ull v) {
    float x, y; f2_unpack(v, x, y); return x + y;
}
#define F2_NEG(v) ((v) ^ 0x8000000080000000ULL)
#define D2U(x) __double_as_longlong(x)
#define U2D(x) __longlong_as_double(x)

// ---------------------------------------------------------------------------
// K1: streaming pass. Block = 8 warps; warp w owns slot (sg*8+w), lanes own
// 32 consecutive float4-chunks of every frame-row -> all pred/gt loads are
// lane-contiguous LDG.64 over a 256B contiguous warp footprint.
// After the T-loop: 3-round smem tree folds the block's 8 slots, then warp 0
// atomically merges per-channel stats into g_red (16 writers/address chip-wide).
// ---------------------------------------------------------------------------
__global__ __launch_bounds__(BLK, 4)
void k_main(const float* __restrict__ pred, const float* __restrict__ gt,
            const float* __restrict__ vis) {
    const unsigned lane = threadIdx.x & 31;
    const unsigned warp = threadIdx.x >> 5;
    const unsigned cg   = blockIdx.x % NCGRP;
    const unsigned sg   = blockIdx.x / NCGRP;
    const unsigned c4   = cg * C4_PER_BLK + lane;
    const unsigned slot = sg * SLOTS_PER_BLK + warp;
    const unsigned b    = slot / TC;
    const unsigned t0   = (slot % TC) * FR;

    const unsigned phi = c4 % 3;               // 4*c4 mod 3 == c4 mod 3
    const unsigned pA  = (4 * c4) / 3;         // first point touched
    const unsigned pB  = pA + 1;               // second point touched
    const bool s1 = (phi == 2);                // pos1 belongs to point B?
    const bool s2 = (phi >= 1);                // pos2 belongs to point B?

    // coord weights per position: coord(pos) = (phi+pos)%3 ; z gets weight 2
    const float w0 = ((phi + 0) % 3 == 2) ? 2.f : 1.f;
    const float w1 = ((phi + 1) % 3 == 2) ? 2.f : 1.f;
    const float w2 = ((phi + 2) % 3 == 2) ? 2.f : 1.f;
    const float w3 = ((phi + 3) % 3 == 2) ? 2.f : 1.f;
    const ull cw_lo = f2_pack(w0, w1);
    const ull cw_hi = f2_pack(w2, w3);

    const double2* __restrict__ pred2 = (const double2*)pred;
    const double2* __restrict__ gt2   = (const double2*)gt;

    // accumulators (f32x2 per channel-pair)
    ull st[10];                                 // cnt,spx,spq,sgx,sgq (lo,hi)
    #pragma unroll
    for (int k = 0; k < 10; k++) st[k] = 0;
    ull recon2 = 0, temp2 = 0, nvel2 = 0;

    // previous-frame state: negated diff and mask
    ull ndplo = 0, ndphi = 0, pmlo = 0, pmhi = 0;

    if (t0 > 0) {  // preload frame t0-1
        unsigned o4 = (b * TT + t0 - 1) * NC4 + c4;
        unsigned ov = (b * TT + t0 - 1) * NPTS;
        double2 p = pred2[o4], g = gt2[o4];
        float vA = vis[ov + pA], vB = vis[ov + pB];
        float mA = (vA > 0.5f) ? 1.f : 0.f;
        float mB = (vB > 0.5f) ? 1.f : 0.f;
        pmlo = f2_pack(mA, s1 ? mB : mA);
        pmhi = f2_pack(s2 ? mB : mA, mB);
        ndplo = f2_add(D2U(g.x), F2_NEG(D2U(p.x)));
        ndphi = f2_add(D2U(g.y), F2_NEG(D2U(p.y)));
    }

    unsigned o4 = (b * TT + t0) * NC4 + c4;
    unsigned ov = (b * TT + t0) * NPTS;

    #pragma unroll 2
    for (unsigned i = 0; i < FR; i++) {
        double2 p = pred2[o4], g = gt2[o4];
        float vA = vis[ov + pA], vB = vis[ov + pB];
        o4 += NC4; ov += NPTS;

        float mA = (vA > 0.5f) ? 1.f : 0.f;
        float mB = (vB > 0.5f) ? 1.f : 0.f;
        ull mmlo = f2_pack(mA, s1 ? mB : mA);
        ull mmhi = f2_pack(s2 ? mB : mA, mB);

        ull plo = D2U(p.x), phi_ = D2U(p.y);
        ull glo = D2U(g.x), ghi_ = D2U(g.y);

        // per-channel moment sums
        ull mp = f2_mul(mmlo, plo);
        st[2] = f2_add(st[2], mp);  st[4] = f2_fma(mp, plo, st[4]);
        mp = f2_mul(mmhi, phi_);
        st[3] = f2_add(st[3], mp);  st[5] = f2_fma(mp, phi_, st[5]);
        mp = f2_mul(mmlo, glo);
        st[6] = f2_add(st[6], mp);  st[8] = f2_fma(mp, glo, st[8]);
        mp = f2_mul(mmhi, ghi_);
        st[7] = f2_add(st[7], mp);  st[9] = f2_fma(mp, ghi_, st[9]);
        st[0] = f2_add(st[0], mmlo);
        st[1] = f2_add(st[1], mmhi);

        // recon: sum w * m * (p-g)^2
        ull dlo = f2_add(plo, F2_NEG(glo));
        ull dhi = f2_add(phi_, F2_NEG(ghi_));
        ull dmlo = f2_mul(dlo, mmlo);
        ull dmhi = f2_mul(dhi, mmhi);
        recon2 = f2_fma(f2_mul(dmlo, cw_lo), dmlo, recon2);
        recon2 = f2_fma(f2_mul(dmhi, cw_hi), dmhi, recon2);

        // temporal: e = d - d_prev, masked by m*m_prev
        ull elo = f2_add(dlo, ndplo);
        ull ehi = f2_add(dhi, ndphi);
        ull vmlo = f2_mul(mmlo, pmlo);
        ull vmhi = f2_mul(mmhi, pmhi);
        temp2 = f2_fma(f2_mul(elo, vmlo), elo, temp2);
        temp2 = f2_fma(f2_mul(ehi, vmhi), ehi, temp2);
        nvel2 = f2_add(nvel2, vmlo);
        nvel2 = f2_add(nvel2, vmhi);    // counts each point 3x -> /3 later

        ndplo = F2_NEG(dlo); ndphi = F2_NEG(dhi);
        pmlo = mmlo; pmhi = mmhi;
    }

    // ---- fold the block's 8 slots (3-round smem tree over warps) ----------
    __shared__ ull sred[4 * 32 * 10];           // 10 KB
    #pragma unroll
    for (int half = 4; half >= 1; half >>= 1) {
        if (warp >= (unsigned)half && warp < (unsigned)(2 * half)) {
            ull* dst = sred + ((warp - half) * 32 + lane) * 10;
            #pragma unroll
            for (int k = 0; k < 10; k++) dst[k] = st[k];
        }
        __syncthreads();
        if (warp < (unsigned)half) {
            const ull* src = sred + (warp * 32 + lane) * 10;
            #pragma unroll
            for (int k = 0; k < 10; k++) st[k] = f2_add(st[k], src[k]);
        }
        __syncthreads();
    }

    // warp 0 merges folded per-channel stats into g_red (float atomics)
    if (warp == 0) {
        float* base = g_red + 4 * c4;
        #pragma unroll
        for (int s = 0; s < 5; s++) {
            float x, y;
            f2_unpack(st[2 * s],     x, y);
            atomicAdd(base + s * NF + 0, x);
            atomicAdd(base + s * NF + 1, y);
            f2_unpack(st[2 * s + 1], x, y);
            atomicAdd(base + s * NF + 2, x);
            atomicAdd(base + s * NF + 3, y);
        }
    }

    // block-reduce recon/temporal/nvel -> per-block partial (no atomics)
    float wr = f2_sum(recon2), wt = f2_sum(temp2), wv = f2_sum(nvel2);
    __shared__ float sm[8][3];
    #pragma unroll
    for (int o = 16; o > 0; o >>= 1) {
        wr += __shfl_down_sync(0xffffffffu, wr, o);
        wt += __shfl_down_sync(0xffffffffu, wt, o);
        wv += __shfl_down_sync(0xffffffffu, wv, o);
    }
    if (lane == 0) { sm[warp][0] = wr; sm[warp][1] = wt; sm[warp][2] = wv; }
    __syncthreads();
    if (threadIdx.x < 3) {
        int k = threadIdx.x;
        float acc = 0.f;
        #pragma unroll
        for (int w = 0; w < 8; w++) acc += sm[w][k];
        g_bsum[blockIdx.x * 3 + k] = acc;
    }
}

// ---------------------------------------------------------------------------
// K2: identity (per-point variance ratio over L2-hot g_red) + block-partial
// fold + adaptive re-weighting, then RE-ZERO g_red for the next replay.
// One block, 1024 threads.
// ---------------------------------------------------------------------------
__global__ __launch_bounds__(1024)
void k_final(float* __restrict__ out) {
    int tid = threadIdx.x;

    float ident = 0.f, cntsum = 0.f;
    #pragma unroll
    for (int rep = 0; rep < 2; rep++) {
        int n = tid + rep * 1024;
        float c  = g_red[3 * n];                      // cnt (channel 3n)
        float dm = fmaxf(c, 1.f);
        float dv = fmaxf(c - 1.f, 1.f);
        float num = 0.f, den = 0.f;
        #pragma unroll
        for (int k = 0; k < 3; k++) {
            int ch = 3 * n + k;
            float sx = g_red[1 * NF + ch];
            float sq = g_red[2 * NF + ch];
            float mean = sx / dm;
            float pv = (sq - 2.f * mean * sx + c * mean * mean) / dv;
            float gx = g_red[3 * NF + ch];
            float gq = g_red[4 * NF + ch];
            float gmean = gx / dm;
            float gv = (gq - 2.f * gmean * gx + c * gmean * gmean) / dv;
            num += fabsf(pv - gv);
            den += gv;
        }
        float vr = num / (den + 1e-6f);
        ident  += (c > 1.f) ? vr : 0.f;
        cntsum += c;
    }

    double racc = 0.0, tacc = 0.0, vacc = 0.0;
    if (tid < NBLK) {
        racc = (double)g_bsum[tid * 3 + 0];
        tacc = (double)g_bsum[tid * 3 + 1];
        vacc = (double)g_bsum[tid * 3 + 2];
    }

    // block reduction of 5 quantities
    __shared__ double sr[5][32];
    double di = ident, dc = cntsum;
    #pragma unroll
    for (int o = 16; o > 0; o >>= 1) {
        di   += __shfl_down_sync(0xffffffffu, di, o);
        dc   += __shfl_down_sync(0xffffffffu, dc, o);
        racc += __shfl_down_sync(0xffffffffu, racc, o);
        tacc += __shfl_down_sync(0xffffffffu, tacc, o);
        vacc += __shfl_down_sync(0xffffffffu, vacc, o);
    }
    int lane = tid & 31, wid = tid >> 5;
    if (lane == 0) {
        sr[0][wid] = di; sr[1][wid] = dc; sr[2][wid] = racc;
        sr[3][wid] = tacc; sr[4][wid] = vacc;
    }
    __syncthreads();   // all g_red reads complete before this barrier

    // re-zero g_red for the next graph replay (30 STGs/thread)
    for (int i = tid; i < NSTAT * NF; i += 1024) g_red[i] = 0.f;

    if (wid == 0) {
        di = sr[0][lane]; dc = sr[1][lane]; racc = sr[2][lane];
        tacc = sr[3][lane]; vacc = sr[4][lane];
        #pragma unroll
        for (int o = 16; o > 0; o >>= 1) {
            di   += __shfl_down_sync(0xffffffffu, di, o);
            dc   += __shfl_down_sync(0xffffffffu, dc, o);
            racc += __shfl_down_sync(0xffffffffu, racc, o);
            tacc += __shfl_down_sync(0xffffffffu, tacc, o);
            vacc += __shfl_down_sync(0xffffffffu, vacc, o);
        }
        if (lane == 0) {
            double nvis = dc;
            double nvel = vacc / 3.0;    // channels triple-count each point
            float recon    = (nvis > 0.0) ? (float)(racc / fmax(nvis, 1.0)) : 0.f;
            float temporal = (nvel > 0.0) ? (float)(tacc / fmax(nvel, 1.0)) : 0.f;
            float identity = (float)(di / (double)NPTS);

            float rl = recon, tl = temporal, il = identity;
            bool  all_pos = (rl > 0.f) && (tl > 0.f) && (il > 0.f);
            float mx     = fmaxf(fmaxf(rl, tl), il);
            float target = mx / 3.f;
            float thresh = 10.f * target;

            float rw = (all_pos && rl > thresh) ? 1.0f * target / fmaxf(rl, 1e-30f) : 1.0f;
            float tw = (all_pos && tl > thresh) ? 0.5f * target / fmaxf(tl, 1e-30f) : 0.5f;
            float iw = (all_pos && il > thresh) ? 0.1f * target / fmaxf(il, 1e-30f) : 0.1f;

            out[0] = rw * recon + tw * temporal + iw * identity;
            out[1] = recon;
            out[2] = temporal;
            out[3] = identity;
        }
    }
}

extern "C" void kernel_launch(void* const* d_in, const int* in_sizes, int n_in,
                              void* d_out, int out_size) {
    const float* pred = (const float*)d_in[0];
    const float* gt   = (const float*)d_in[1];
    const float* vis  = (const float*)d_in[2];
    float* out = (float*)d_out;

    k_main<<<NBLK, BLK>>>(pred, gt, vis);
    k_final<<<1, 1024>>>(out);
}